// round 1
// baseline (speedup 1.0000x reference)
#include <cuda_runtime.h>
#include <cuda_bf16.h>
#include <math.h>

// ---------------------------------------------------------------------------
// Problem constants: B=1, C=64, H=W=64, N=4096, heads=8, dh=8, inner=64,
// hid_lc=32, hid_f=256. All activations fp32 in [channel][pixel] layout.
// ---------------------------------------------------------------------------

constexpr int NPIX = 4096;

// Scratch buffer offsets (floats) inside one big __device__ array.
constexpr int OFF_XN   = 0;                       // 64*4096   ln1 out
constexpr int OFF_QKV  = OFF_XN   + 64  * NPIX;   // 192*4096  qkv conv out
constexpr int OFF_QKVM = OFF_QKV  + 192 * NPIX;   // 192*4096  modulated qkv
constexpr int OFF_H1   = OFF_QKVM + 192 * NPIX;   // 32*4096   lc1 out
constexpr int OFF_H2   = OFF_H1   + 32  * NPIX;   // 32*4096   lc2 out
constexpr int OFF_GAM  = OFF_H2   + 32  * NPIX;   // 64*4096
constexpr int OFF_BET  = OFF_GAM  + 64  * NPIX;   // 64*4096
constexpr int OFF_INVL = OFF_BET  + 64  * NPIX;   // 4096
constexpr int OFF_MEAN = OFF_INVL + NPIX;         // 1 (padded)
constexpr int OFF_PM   = OFF_MEAN + 64;           // 4*8*4096  partial max
constexpr int OFF_PL   = OFF_PM   + 4*8*NPIX;     // 4*8*4096  partial sum
constexpr int OFF_PACC = OFF_PL   + 4*8*NPIX;     // 4*64*4096 partial acc
constexpr int OFF_AO   = OFF_PACC + 4*64*NPIX;    // 64*4096   attention out
constexpr int OFF_X2   = OFF_AO   + 64  * NPIX;   // 64*4096   x + proj
constexpr int OFF_YN   = OFF_X2   + 64  * NPIX;   // 64*4096   ln2 out
constexpr int OFF_Y1   = OFF_YN   + 64  * NPIX;   // 256*4096  ffn1 out
constexpr int OFF_Y2   = OFF_Y1   + 256 * NPIX;   // 256*4096  dw+gelu out
constexpr int TOTAL_F  = OFF_Y2   + 256 * NPIX;

__device__ float g_buf[TOTAL_F];

// ---------------------------------------------------------------------------
// Per-pixel LayerNorm over 64 channels. 1 thread = 1 pixel, coalesced.
// ---------------------------------------------------------------------------
__global__ void ln_kernel(const float* __restrict__ x, const float* __restrict__ w,
                          const float* __restrict__ b, float* __restrict__ out) {
    int n = blockIdx.x * 256 + threadIdx.x;
    float v[64];
    float s = 0.f;
#pragma unroll
    for (int c = 0; c < 64; c++) { v[c] = x[(c << 12) + n]; s += v[c]; }
    float mu = s * (1.f / 64.f);
    float ss = 0.f;
#pragma unroll
    for (int c = 0; c < 64; c++) { float d = v[c] - mu; ss = fmaf(d, d, ss); }
    float rs = rsqrtf(ss * (1.f / 64.f) + 1e-5f);
#pragma unroll
    for (int c = 0; c < 64; c++)
        out[(c << 12) + n] = (v[c] - mu) * rs * w[c] + b[c];
}

// ---------------------------------------------------------------------------
// 1x1 conv = GEMM: Y[M x 4096] = W[M x K] @ X[K x 4096] + bias (+ residual).
// CTA: 32 rows x 256 pixels. Weights tile in smem (uniform broadcast reads).
// ---------------------------------------------------------------------------
template <int K>
__global__ void gemm_kernel(const float* __restrict__ W, const float* __restrict__ bias,
                            const float* __restrict__ X, float* __restrict__ Y,
                            const float* __restrict__ res) {
    __shared__ float ws[32 * K];
    const int row0 = blockIdx.y * 32;
    for (int i = threadIdx.x; i < 32 * K; i += 256) ws[i] = W[row0 * K + i];
    __syncthreads();
    const int n = blockIdx.x * 256 + threadIdx.x;
    float acc[32];
#pragma unroll
    for (int r = 0; r < 32; r++) acc[r] = 0.f;
#pragma unroll 4
    for (int k = 0; k < K; k++) {
        float xv = __ldg(X + (k << 12) + n);
#pragma unroll
        for (int r = 0; r < 32; r++) acc[r] = fmaf(ws[r * K + k], xv, acc[r]);
    }
#pragma unroll
    for (int r = 0; r < 32; r++) {
        float o = acc[r] + bias[row0 + r];
        if (res) o += res[((row0 + r) << 12) + n];
        Y[((row0 + r) << 12) + n] = o;
    }
}

// ---------------------------------------------------------------------------
// lc1: conv 1->32, 3x3, pad 1, relu
// ---------------------------------------------------------------------------
__global__ void lc1_kernel(const float* __restrict__ luma, const float* __restrict__ w,
                           const float* __restrict__ b) {
    int idx = blockIdx.x * 256 + threadIdx.x;      // 32*4096
    int oc = idx >> 12, n = idx & 4095;
    int y = n >> 6, x = n & 63;
    float s = b[oc];
#pragma unroll
    for (int ky = 0; ky < 3; ky++) {
        int iy = y + ky - 1;
        if ((unsigned)iy < 64u) {
#pragma unroll
            for (int kx = 0; kx < 3; kx++) {
                int ix = x + kx - 1;
                if ((unsigned)ix < 64u)
                    s = fmaf(w[oc * 9 + ky * 3 + kx], luma[iy * 64 + ix], s);
            }
        }
    }
    g_buf[OFF_H1 + idx] = fmaxf(s, 0.f);
}

// ---------------------------------------------------------------------------
// lc2: conv 32->32, 3x3, pad 1, relu
// ---------------------------------------------------------------------------
__global__ void lc2_kernel(const float* __restrict__ w, const float* __restrict__ b) {
    int idx = blockIdx.x * 256 + threadIdx.x;      // 32*4096
    int oc = idx >> 12, n = idx & 4095;
    int y = n >> 6, x = n & 63;
    float s = b[oc];
    for (int ic = 0; ic < 32; ic++) {
        const float* in = g_buf + OFF_H1 + (ic << 12);
        const float* wp = w + (oc * 32 + ic) * 9;
#pragma unroll
        for (int ky = 0; ky < 3; ky++) {
            int iy = y + ky - 1;
            if ((unsigned)iy < 64u) {
#pragma unroll
                for (int kx = 0; kx < 3; kx++) {
                    int ix = x + kx - 1;
                    if ((unsigned)ix < 64u)
                        s = fmaf(wp[ky * 3 + kx], in[iy * 64 + ix], s);
                }
            }
        }
    }
    g_buf[OFF_H2 + idx] = fmaxf(s, 0.f);
}

// ---------------------------------------------------------------------------
// invL = avgpool3x3(1 - luma), zero padding, fixed /9
// ---------------------------------------------------------------------------
__global__ void pool_kernel(const float* __restrict__ luma) {
    int n = blockIdx.x * 256 + threadIdx.x;
    int y = n >> 6, x = n & 63;
    float s = 0.f;
#pragma unroll
    for (int dy = -1; dy <= 1; dy++) {
        int iy = y + dy;
        if ((unsigned)iy < 64u) {
#pragma unroll
            for (int dx = -1; dx <= 1; dx++) {
                int ix = x + dx;
                if ((unsigned)ix < 64u) s += 1.0f - luma[iy * 64 + ix];
            }
        }
    }
    g_buf[OFF_INVL + n] = s * (1.0f / 9.0f);
}

__global__ void mean_kernel() {
    __shared__ float sm[1024];
    float s = 0.f;
    for (int i = threadIdx.x; i < NPIX; i += 1024) s += g_buf[OFF_INVL + i];
    sm[threadIdx.x] = s;
    __syncthreads();
    for (int st = 512; st > 0; st >>= 1) {
        if (threadIdx.x < st) sm[threadIdx.x] += sm[threadIdx.x + st];
        __syncthreads();
    }
    if (threadIdx.x == 0) g_buf[OFF_MEAN] = sm[0] * (1.0f / 4096.0f);
}

// ---------------------------------------------------------------------------
// Modulation: qkvm[c][n] = g[c&63][n]*qkv[c][n] + bt[c&63][n]
//             (+ alpha*(invL[n]-mean) for q channels c<64)
// ---------------------------------------------------------------------------
__global__ void modulate_kernel(const float* __restrict__ alpha_p) {
    int idx = blockIdx.x * 256 + threadIdx.x;      // 192*4096
    int c = idx >> 12, n = idx & 4095;
    int cg = c & 63;
    float g = g_buf[OFF_GAM + (cg << 12) + n];
    float bt = g_buf[OFF_BET + (cg << 12) + n];
    float v = fmaf(g, g_buf[OFF_QKV + idx], bt);
    if (c < 64) v = fmaf(alpha_p[0], g_buf[OFF_INVL + n] - g_buf[OFF_MEAN], v);
    g_buf[OFF_QKVM + idx] = v;
}

// ---------------------------------------------------------------------------
// Flash attention (fp32 SIMT, exp2 domain). Grid (8 qblocks, 8 heads, 4 ksplits),
// 128 threads, 4 queries/thread. Each CTA scans 1024 keys (2 smem tiles of 512),
// writes split-local (m, l, acc) partials; combine kernel merges the 4 splits.
// ---------------------------------------------------------------------------
__global__ void attn_kernel() {
    __shared__ __align__(16) float ks[4096];   // [j][d], 512 x 8
    __shared__ __align__(16) float vs[4096];
    const int h = blockIdx.y;
    const int n0 = blockIdx.x * 512;
    const int z = blockIdx.z;
    const float* qp = g_buf + OFF_QKVM + (h * 8) * NPIX;
    const float* kp = g_buf + OFF_QKVM + (64 + h * 8) * NPIX;
    const float* vp = g_buf + OFF_QKVM + (128 + h * 8) * NPIX;
    const float sc = 0.35355339059327373f * 1.4426950408889634f;  // dh^-0.5 * log2(e)

    float q[4][8], acc[4][8], m[4], l[4];
#pragma unroll
    for (int i = 0; i < 4; i++) {
        int n = n0 + threadIdx.x + i * 128;
#pragma unroll
        for (int d = 0; d < 8; d++) { q[i][d] = qp[(d << 12) + n] * sc; acc[i][d] = 0.f; }
        m[i] = -1e30f; l[i] = 0.f;
    }

    for (int t = 0; t < 2; t++) {
        int jt = z * 1024 + t * 512;
        __syncthreads();
        for (int i = threadIdx.x; i < 4096; i += 128) {
            int d = i >> 9, j = i & 511;
            ks[j * 8 + d] = kp[(d << 12) + jt + j];
            vs[j * 8 + d] = vp[(d << 12) + jt + j];
        }
        __syncthreads();
        for (int j = 0; j < 512; j++) {
            float4 ka = *(const float4*)(ks + j * 8);
            float4 kb = *(const float4*)(ks + j * 8 + 4);
            float4 va = *(const float4*)(vs + j * 8);
            float4 vb = *(const float4*)(vs + j * 8 + 4);
#pragma unroll
            for (int i = 0; i < 4; i++) {
                float s = q[i][0] * ka.x;
                s = fmaf(q[i][1], ka.y, s); s = fmaf(q[i][2], ka.z, s); s = fmaf(q[i][3], ka.w, s);
                s = fmaf(q[i][4], kb.x, s); s = fmaf(q[i][5], kb.y, s);
                s = fmaf(q[i][6], kb.z, s); s = fmaf(q[i][7], kb.w, s);
                if (s > m[i]) {  // rare after warmup: predicated rescale path
                    float corr = exp2f(m[i] - s);
                    m[i] = s; l[i] *= corr;
#pragma unroll
                    for (int d = 0; d < 8; d++) acc[i][d] *= corr;
                }
                float p = exp2f(s - m[i]);
                l[i] += p;
                acc[i][0] = fmaf(p, va.x, acc[i][0]); acc[i][1] = fmaf(p, va.y, acc[i][1]);
                acc[i][2] = fmaf(p, va.z, acc[i][2]); acc[i][3] = fmaf(p, va.w, acc[i][3]);
                acc[i][4] = fmaf(p, vb.x, acc[i][4]); acc[i][5] = fmaf(p, vb.y, acc[i][5]);
                acc[i][6] = fmaf(p, vb.z, acc[i][6]); acc[i][7] = fmaf(p, vb.w, acc[i][7]);
            }
        }
    }

    float* pm = g_buf + OFF_PM;
    float* pl = g_buf + OFF_PL;
    float* pacc = g_buf + OFF_PACC;
#pragma unroll
    for (int i = 0; i < 4; i++) {
        int n = n0 + threadIdx.x + i * 128;
        pm[((z * 8 + h) << 12) + n] = m[i];
        pl[((z * 8 + h) << 12) + n] = l[i];
#pragma unroll
        for (int d = 0; d < 8; d++)
            pacc[((z * 64 + h * 8 + d) << 12) + n] = acc[i][d];
    }
}

__global__ void combine_kernel() {
    int idx = blockIdx.x * 256 + threadIdx.x;      // 8 heads * 4096
    int h = idx >> 12, n = idx & 4095;
    const float* pm = g_buf + OFF_PM;
    const float* pl = g_buf + OFF_PL;
    const float* pacc = g_buf + OFF_PACC;
    float mv[4], M = -1e30f;
#pragma unroll
    for (int s = 0; s < 4; s++) { mv[s] = pm[((s * 8 + h) << 12) + n]; M = fmaxf(M, mv[s]); }
    float L = 0.f, w[4];
#pragma unroll
    for (int s = 0; s < 4; s++) {
        w[s] = exp2f(mv[s] - M);
        L = fmaf(pl[((s * 8 + h) << 12) + n], w[s], L);
    }
    float rL = 1.0f / L;
#pragma unroll
    for (int d = 0; d < 8; d++) {
        float o = 0.f;
#pragma unroll
        for (int s = 0; s < 4; s++)
            o = fmaf(pacc[((s * 64 + h * 8 + d) << 12) + n], w[s], o);
        g_buf[OFF_AO + ((h * 8 + d) << 12) + n] = o * rL;
    }
}

// ---------------------------------------------------------------------------
// Depthwise 3x3 conv (pad 1) + exact GELU
// ---------------------------------------------------------------------------
__global__ void dwgelu_kernel(const float* __restrict__ w, const float* __restrict__ b) {
    int idx = blockIdx.x * 256 + threadIdx.x;      // 256*4096
    int c = idx >> 12, n = idx & 4095;
    int y = n >> 6, x = n & 63;
    const float* in = g_buf + OFF_Y1 + (c << 12);
    float s = b[c];
#pragma unroll
    for (int ky = 0; ky < 3; ky++) {
        int iy = y + ky - 1;
        if ((unsigned)iy < 64u) {
#pragma unroll
            for (int kx = 0; kx < 3; kx++) {
                int ix = x + kx - 1;
                if ((unsigned)ix < 64u)
                    s = fmaf(w[c * 9 + ky * 3 + kx], in[iy * 64 + ix], s);
            }
        }
    }
    g_buf[OFF_Y2 + idx] = 0.5f * s * (1.0f + erff(s * 0.7071067811865476f));
}

// ---------------------------------------------------------------------------
// Launch
// ---------------------------------------------------------------------------
extern "C" void kernel_launch(void* const* d_in, const int* in_sizes, int n_in,
                              void* d_out, int out_size) {
    const float* x      = (const float*)d_in[0];
    const float* luma   = (const float*)d_in[1];
    const float* ln1_w  = (const float*)d_in[2];
    const float* ln1_b  = (const float*)d_in[3];
    const float* qkv_w  = (const float*)d_in[4];
    const float* qkv_b  = (const float*)d_in[5];
    const float* proj_w = (const float*)d_in[6];
    const float* proj_b = (const float*)d_in[7];
    const float* lc1_w  = (const float*)d_in[8];
    const float* lc1_b  = (const float*)d_in[9];
    const float* lc2_w  = (const float*)d_in[10];
    const float* lc2_b  = (const float*)d_in[11];
    const float* gam_w  = (const float*)d_in[12];
    const float* gam_b  = (const float*)d_in[13];
    const float* bet_w  = (const float*)d_in[14];
    const float* bet_b  = (const float*)d_in[15];
    const float* alpha  = (const float*)d_in[16];
    const float* ln2_w  = (const float*)d_in[17];
    const float* ln2_b  = (const float*)d_in[18];
    const float* ffn1_w = (const float*)d_in[19];
    const float* ffn1_b = (const float*)d_in[20];
    const float* dw_w   = (const float*)d_in[21];
    const float* dw_b   = (const float*)d_in[22];
    const float* ffn2_w = (const float*)d_in[23];
    const float* ffn2_b = (const float*)d_in[24];
    float* out = (float*)d_out;

    float* buf = nullptr;
    cudaGetSymbolAddress((void**)&buf, g_buf);

    // --- attention branch ---
    ln_kernel<<<16, 256>>>(x, ln1_w, ln1_b, buf + OFF_XN);
    gemm_kernel<64><<<dim3(16, 6), 256>>>(qkv_w, qkv_b, buf + OFF_XN, buf + OFF_QKV, nullptr);
    lc1_kernel<<<512, 256>>>(luma, lc1_w, lc1_b);
    lc2_kernel<<<512, 256>>>(lc2_w, lc2_b);
    gemm_kernel<32><<<dim3(16, 2), 256>>>(gam_w, gam_b, buf + OFF_H2, buf + OFF_GAM, nullptr);
    gemm_kernel<32><<<dim3(16, 2), 256>>>(bet_w, bet_b, buf + OFF_H2, buf + OFF_BET, nullptr);
    pool_kernel<<<16, 256>>>(luma);
    mean_kernel<<<1, 1024>>>();
    modulate_kernel<<<3072, 256>>>(alpha);
    attn_kernel<<<dim3(8, 8, 4), 128>>>();
    combine_kernel<<<128, 256>>>();
    gemm_kernel<64><<<dim3(16, 2), 256>>>(proj_w, proj_b, buf + OFF_AO, buf + OFF_X2, x);

    // --- ConvFFN branch ---
    ln_kernel<<<16, 256>>>(buf + OFF_X2, ln2_w, ln2_b, buf + OFF_YN);
    gemm_kernel<64><<<dim3(16, 8), 256>>>(ffn1_w, ffn1_b, buf + OFF_YN, buf + OFF_Y1, nullptr);
    dwgelu_kernel<<<4096, 256>>>(dw_w, dw_b);
    gemm_kernel<256><<<dim3(16, 2), 256>>>(ffn2_w, ffn2_b, buf + OFF_Y2, out, buf + OFF_X2);
}

// round 2
// speedup vs baseline: 1.4763x; 1.4763x over previous
#include <cuda_runtime.h>
#include <cuda_bf16.h>
#include <math.h>

// ---------------------------------------------------------------------------
// B=1, C=64, H=W=64, N=4096, heads=8, dh=8, inner=64, hid_lc=32, hid_f=256.
// Activations fp32, [channel][pixel] layout.
// ---------------------------------------------------------------------------

constexpr int NPIX = 4096;

constexpr int OFF_XN   = 0;                       // 64*4096
constexpr int OFF_QKV  = OFF_XN   + 64  * NPIX;   // 192*4096
constexpr int OFF_QKVM = OFF_QKV  + 192 * NPIX;   // 192*4096
constexpr int OFF_H1   = OFF_QKVM + 192 * NPIX;   // 32*4096
constexpr int OFF_H2   = OFF_H1   + 32  * NPIX;   // 32*4096
constexpr int OFF_GAM  = OFF_H2   + 32  * NPIX;   // 64*4096
constexpr int OFF_BET  = OFF_GAM  + 64  * NPIX;   // 64*4096
constexpr int OFF_INVL = OFF_BET  + 64  * NPIX;   // 4096
constexpr int OFF_MEAN = OFF_INVL + NPIX;         // [0]=mean, [8..15]=maxK^2/head
constexpr int OFF_KN   = OFF_MEAN + 8;
constexpr int OFF_PL   = OFF_MEAN + 64;           // 4*8*4096 split partial sums
constexpr int OFF_PACC = OFF_PL   + 4*8*NPIX;     // 4*64*4096 split partial acc
constexpr int OFF_AO   = OFF_PACC + 4*64*NPIX;    // 64*4096
constexpr int OFF_X2   = OFF_AO   + 64  * NPIX;   // 64*4096
constexpr int OFF_YN   = OFF_X2   + 64  * NPIX;   // 64*4096
constexpr int OFF_Y1   = OFF_YN   + 64  * NPIX;   // 256*4096
constexpr int OFF_Y2   = OFF_Y1   + 256 * NPIX;   // 256*4096
constexpr int TOTAL_F  = OFF_Y2   + 256 * NPIX;

__device__ float g_buf[TOTAL_F];

// ---------------- packed f32x2 helpers (sm_100+) ----------------------------
typedef unsigned long long u64;
__device__ __forceinline__ u64 pack2(float lo, float hi) {
    u64 r; asm("mov.b64 %0,{%1,%2};" : "=l"(r) : "f"(lo), "f"(hi)); return r;
}
__device__ __forceinline__ float2 unpack2(u64 v) {
    float2 r; asm("mov.b64 {%0,%1},%2;" : "=f"(r.x), "=f"(r.y) : "l"(v)); return r;
}
__device__ __forceinline__ u64 fma2(u64 a, u64 b, u64 c) {
    u64 d; asm("fma.rn.f32x2 %0,%1,%2,%3;" : "=l"(d) : "l"(a), "l"(b), "l"(c)); return d;
}
__device__ __forceinline__ u64 mul2(u64 a, u64 b) {
    u64 d; asm("mul.rn.f32x2 %0,%1,%2;" : "=l"(d) : "l"(a), "l"(b)); return d;
}
__device__ __forceinline__ float ex2f(float x) {
    float y; asm("ex2.approx.f32 %0,%1;" : "=f"(y) : "f"(x)); return y;
}

// ---------------------------------------------------------------------------
// Per-pixel LayerNorm over 64 channels.
// ---------------------------------------------------------------------------
__global__ void ln_kernel(const float* __restrict__ x, const float* __restrict__ w,
                          const float* __restrict__ b, float* __restrict__ out) {
    int n = blockIdx.x * 256 + threadIdx.x;
    float v[64];
    float s = 0.f;
#pragma unroll
    for (int c = 0; c < 64; c++) { v[c] = x[(c << 12) + n]; s += v[c]; }
    float mu = s * (1.f / 64.f);
    float ss = 0.f;
#pragma unroll
    for (int c = 0; c < 64; c++) { float d = v[c] - mu; ss = fmaf(d, d, ss); }
    float rs = rsqrtf(ss * (1.f / 64.f) + 1e-5f);
#pragma unroll
    for (int c = 0; c < 64; c++)
        out[(c << 12) + n] = (v[c] - mu) * rs * w[c] + b[c];
}

// ---------------------------------------------------------------------------
// 1x1 conv GEMM, 16 output rows per CTA, packed f32x2 accumulators.
// ---------------------------------------------------------------------------
template <int K>
__global__ void gemm16_kernel(const float* __restrict__ W, const float* __restrict__ bias,
                              const float* __restrict__ X, float* __restrict__ Y,
                              const float* __restrict__ res) {
    __shared__ u64 ws2[8 * K];  // [rowpair p][k] = (W[2p][k], W[2p+1][k])
    const int row0 = blockIdx.y * 16;
    for (int i = threadIdx.x; i < 8 * K; i += 256) {
        int p = i / K, k = i - p * K;
        ws2[i] = pack2(W[(row0 + 2 * p) * K + k], W[(row0 + 2 * p + 1) * K + k]);
    }
    __syncthreads();
    const int n = blockIdx.x * 256 + threadIdx.x;
    u64 acc[8];
#pragma unroll
    for (int p = 0; p < 8; p++) acc[p] = 0ULL;
#pragma unroll 4
    for (int k = 0; k < K; k++) {
        float xv = __ldg(X + (k << 12) + n);
        u64 x2 = pack2(xv, xv);
#pragma unroll
        for (int p = 0; p < 8; p++) acc[p] = fma2(ws2[p * K + k], x2, acc[p]);
    }
#pragma unroll
    for (int p = 0; p < 8; p++) {
        float2 a = unpack2(acc[p]);
        int r0 = row0 + 2 * p;
        float o0 = a.x + bias[r0], o1 = a.y + bias[r0 + 1];
        if (res) { o0 += res[(r0 << 12) + n]; o1 += res[((r0 + 1) << 12) + n]; }
        Y[(r0 << 12) + n] = o0;
        Y[((r0 + 1) << 12) + n] = o1;
    }
}

// ---------------------------------------------------------------------------
// lc1: conv 1->32, 3x3, pad 1, relu (luma is 16KB, L1-resident; keep naive)
// ---------------------------------------------------------------------------
__global__ void lc1_kernel(const float* __restrict__ luma, const float* __restrict__ w,
                           const float* __restrict__ b) {
    int idx = blockIdx.x * 256 + threadIdx.x;
    int oc = idx >> 12, n = idx & 4095;
    int y = n >> 6, x = n & 63;
    float s = b[oc];
#pragma unroll
    for (int ky = 0; ky < 3; ky++) {
        int iy = y + ky - 1;
        if ((unsigned)iy < 64u) {
#pragma unroll
            for (int kx = 0; kx < 3; kx++) {
                int ix = x + kx - 1;
                if ((unsigned)ix < 64u)
                    s = fmaf(w[oc * 9 + ky * 3 + kx], luma[iy * 64 + ix], s);
            }
        }
    }
    g_buf[OFF_H1 + idx] = fmaxf(s, 0.f);
}

// ---------------------------------------------------------------------------
// lc2: conv 32->32 3x3 pad1 relu. Tiled: 128 CTAs = 64 spatial 8x8 tiles x
// 2 oc-halves. Input tile + weights in smem; 4 outputs/thread from registers.
// ---------------------------------------------------------------------------
__global__ void lc2_tiled_kernel(const float* __restrict__ w, const float* __restrict__ b) {
    __shared__ float sin[32][10][12];   // [ic][y][x], padded pitch 12
    __shared__ float ws[16][32][12];    // [ocl][ic][9 padded to 12]
    const int bx = blockIdx.x;
    const int tile = bx >> 1, oh = bx & 1;
    const int ty0 = (tile >> 3) * 8, tx0 = (tile & 7) * 8;
    const int tid = threadIdx.x;

    for (int i = tid; i < 16 * 32 * 9; i += 256) {
        int ocl = i / 288, r = i - ocl * 288;
        int ic = r / 9, k = r - ic * 9;
        ws[ocl][ic][k] = w[((oh * 16 + ocl) * 32 + ic) * 9 + k];
    }
    for (int i = tid; i < 3200; i += 256) {
        int ic = i / 100, r = i - ic * 100;
        int yy = r / 10, xx = r - yy * 10;
        int gy = ty0 + yy - 1, gx = tx0 + xx - 1;
        float v = 0.f;
        if ((unsigned)gy < 64u && (unsigned)gx < 64u)
            v = g_buf[OFF_H1 + (ic << 12) + gy * 64 + gx];
        sin[ic][yy][xx] = v;
    }
    __syncthreads();

    const int ocl = tid >> 4, pg = tid & 15;
    const int py = pg >> 1, px = (pg & 1) * 4;
    const int oc = oh * 16 + ocl;
    float acc[4];
    float bb = b[oc];
#pragma unroll
    for (int o = 0; o < 4; o++) acc[o] = bb;

    for (int ic = 0; ic < 32; ic++) {
        const float* base = &sin[ic][py][0];
        float c[3][8];
#pragma unroll
        for (int r = 0; r < 3; r++) {
            float4 a0 = *(const float4*)(base + r * 12 + px);
            float4 a1 = *(const float4*)(base + r * 12 + px + 4);
            c[r][0] = a0.x; c[r][1] = a0.y; c[r][2] = a0.z; c[r][3] = a0.w;
            c[r][4] = a1.x; c[r][5] = a1.y; c[r][6] = a1.z; c[r][7] = a1.w;
        }
        const float* wr = &ws[ocl][ic][0];
        float4 w0 = *(const float4*)wr;
        float4 w1 = *(const float4*)(wr + 4);
        float w8 = wr[8];
        float wk[9] = {w0.x, w0.y, w0.z, w0.w, w1.x, w1.y, w1.z, w1.w, w8};
#pragma unroll
        for (int ky = 0; ky < 3; ky++)
#pragma unroll
            for (int kx = 0; kx < 3; kx++) {
                float wv = wk[ky * 3 + kx];
#pragma unroll
                for (int o = 0; o < 4; o++) acc[o] = fmaf(wv, c[ky][kx + o], acc[o]);
            }
    }
    int gy = ty0 + py, gx = tx0 + px;
#pragma unroll
    for (int o = 0; o < 4; o++)
        g_buf[OFF_H2 + (oc << 12) + gy * 64 + gx + o] = fmaxf(acc[o], 0.f);
}

// ---------------------------------------------------------------------------
// pool (avgpool3x3 of 1-luma, /9) + global mean, single block.
// ---------------------------------------------------------------------------
__global__ void pool_mean_kernel(const float* __restrict__ luma) {
    __shared__ float sm[1024];
    int tid = threadIdx.x;
    float tot = 0.f;
    for (int q = 0; q < 4; q++) {
        int n = tid + q * 1024;
        int y = n >> 6, x = n & 63;
        float s = 0.f;
#pragma unroll
        for (int dy = -1; dy <= 1; dy++) {
            int iy = y + dy;
            if ((unsigned)iy < 64u) {
#pragma unroll
                for (int dx = -1; dx <= 1; dx++) {
                    int ix = x + dx;
                    if ((unsigned)ix < 64u) s += 1.0f - luma[iy * 64 + ix];
                }
            }
        }
        s *= (1.0f / 9.0f);
        g_buf[OFF_INVL + n] = s;
        tot += s;
    }
    sm[tid] = tot;
    __syncthreads();
    for (int st = 512; st > 0; st >>= 1) {
        if (tid < st) sm[tid] += sm[tid + st];
        __syncthreads();
    }
    if (tid == 0) g_buf[OFF_MEAN] = sm[0] * (1.0f / 4096.0f);
}

// ---------------------------------------------------------------------------
// Modulation of q,k,v + alpha luma bias on q.
// ---------------------------------------------------------------------------
__global__ void modulate_kernel(const float* __restrict__ alpha_p) {
    int idx = blockIdx.x * 256 + threadIdx.x;      // 192*4096
    int c = idx >> 12, n = idx & 4095;
    int cg = c & 63;
    float g = g_buf[OFF_GAM + (cg << 12) + n];
    float bt = g_buf[OFF_BET + (cg << 12) + n];
    float v = fmaf(g, g_buf[OFF_QKV + idx], bt);
    if (c < 64) v = fmaf(alpha_p[0], g_buf[OFF_INVL + n] - g_buf[OFF_MEAN], v);
    g_buf[OFF_QKVM + idx] = v;
}

// ---------------------------------------------------------------------------
// Per-head max ||k||^2 (for the Cauchy-Schwarz softmax bound).
// ---------------------------------------------------------------------------
__global__ void knorm_kernel() {
    __shared__ float sm[256];
    int h = blockIdx.x, tid = threadIdx.x;
    const float* kp = g_buf + OFF_QKVM + (64 + h * 8) * NPIX;
    float mx = 0.f;
    for (int j = tid; j < NPIX; j += 256) {
        float ss = 0.f;
#pragma unroll
        for (int d = 0; d < 8; d++) { float v = kp[(d << 12) + j]; ss = fmaf(v, v, ss); }
        mx = fmaxf(mx, ss);
    }
    sm[tid] = mx;
    __syncthreads();
    for (int st = 128; st > 0; st >>= 1) {
        if (tid < st) sm[tid] = fmaxf(sm[tid], sm[tid + st]);
        __syncthreads();
    }
    if (tid == 0) g_buf[OFF_KN + h] = sm[0];
}

// ---------------------------------------------------------------------------
// Flash attention, packed f32x2, fixed per-query softmax bound (branch-free),
// key-split z=4 with plain-sum combine. Grid (8 qblk, 8 heads, 4 ksplit),
// 128 threads, 4 queries/thread.
// ---------------------------------------------------------------------------
__global__ void __launch_bounds__(128) attn_kernel() {
    __shared__ __align__(16) float ks[4096];   // [j][d] 512x8
    __shared__ __align__(16) float vs[4096];
    const int h = blockIdx.y, z = blockIdx.z;
    const int n0 = blockIdx.x * 512;
    const int tid = threadIdx.x;
    const float* qp = g_buf + OFF_QKVM + (h * 8) * NPIX;
    const float* kp = g_buf + OFF_QKVM + (64 + h * 8) * NPIX;
    const float* vp = g_buf + OFF_QKVM + (128 + h * 8) * NPIX;
    const float kn2 = g_buf[OFF_KN + h];
    const float sc = 0.35355339059327373f * 1.4426950408889634f;  // dh^-0.5 * log2(e)

    u64 q2[4][4], acc2[4][4];
    float M[4], l[4];
#pragma unroll
    for (int i = 0; i < 4; i++) {
        int n = n0 + tid + i * 128;
        float qv[8], qn2 = 0.f;
#pragma unroll
        for (int d = 0; d < 8; d++) { qv[d] = qp[(d << 12) + n] * sc; qn2 = fmaf(qv[d], qv[d], qn2); }
        M[i] = sqrtf(qn2 * kn2);   // >= any score (Cauchy-Schwarz), identical across splits
        l[i] = 0.f;
        q2[i][0] = pack2(qv[0], qv[1]); q2[i][1] = pack2(qv[2], qv[3]);
        q2[i][2] = pack2(qv[4], qv[5]); q2[i][3] = pack2(qv[6], qv[7]);
#pragma unroll
        for (int p = 0; p < 4; p++) acc2[i][p] = 0ULL;
    }

    for (int t = 0; t < 2; t++) {
        int jt = z * 1024 + t * 512;
        __syncthreads();
        for (int i2 = tid; i2 < 4096; i2 += 128) {
            int d = i2 >> 9, j = i2 & 511;
            ks[j * 8 + d] = kp[(d << 12) + jt + j];
            vs[j * 8 + d] = vp[(d << 12) + jt + j];
        }
        __syncthreads();
        const ulonglong2* k2p = (const ulonglong2*)ks;
        const ulonglong2* v2p = (const ulonglong2*)vs;
        ulonglong2 ka = k2p[0], kb = k2p[1], va = v2p[0], vb = v2p[1];
        for (int j = 0; j < 512; j++) {
            int jn = (j + 1) & 511;   // prefetch next row (broadcast LDS)
            ulonglong2 nka = k2p[jn * 2], nkb = k2p[jn * 2 + 1];
            ulonglong2 nva = v2p[jn * 2], nvb = v2p[jn * 2 + 1];
#pragma unroll
            for (int i = 0; i < 4; i++) {
                u64 s2 = fma2(q2[i][0], ka.x,
                         fma2(q2[i][1], ka.y,
                         fma2(q2[i][2], kb.x,
                         mul2(q2[i][3], kb.y))));
                float2 sf = unpack2(s2);
                float p = ex2f(sf.x + sf.y - M[i]);
                l[i] += p;
                u64 p2 = pack2(p, p);
                acc2[i][0] = fma2(p2, va.x, acc2[i][0]);
                acc2[i][1] = fma2(p2, va.y, acc2[i][1]);
                acc2[i][2] = fma2(p2, vb.x, acc2[i][2]);
                acc2[i][3] = fma2(p2, vb.y, acc2[i][3]);
            }
            ka = nka; kb = nkb; va = nva; vb = nvb;
        }
    }

    float* pl = g_buf + OFF_PL;
    float* pacc = g_buf + OFF_PACC;
#pragma unroll
    for (int i = 0; i < 4; i++) {
        int n = n0 + tid + i * 128;
        pl[((z * 8 + h) << 12) + n] = l[i];
#pragma unroll
        for (int p = 0; p < 4; p++) {
            float2 a = unpack2(acc2[i][p]);
            pacc[((z * 64 + h * 8 + 2 * p) << 12) + n] = a.x;
            pacc[((z * 64 + h * 8 + 2 * p + 1) << 12) + n] = a.y;
        }
    }
}

__global__ void combine_kernel() {
    int idx = blockIdx.x * 256 + threadIdx.x;      // 8 heads * 4096
    int h = idx >> 12, n = idx & 4095;
    const float* pl = g_buf + OFF_PL;
    const float* pacc = g_buf + OFF_PACC;
    float L = 1e-35f;
#pragma unroll
    for (int s = 0; s < 4; s++) L += pl[((s * 8 + h) << 12) + n];
    float rL = 1.0f / L;
#pragma unroll
    for (int d = 0; d < 8; d++) {
        float o = 0.f;
#pragma unroll
        for (int s = 0; s < 4; s++) o += pacc[((s * 64 + h * 8 + d) << 12) + n];
        g_buf[OFF_AO + ((h * 8 + d) << 12) + n] = o * rL;
    }
}

// ---------------------------------------------------------------------------
// Depthwise 3x3 conv + exact GELU, one CTA per channel with smem halo tile.
// ---------------------------------------------------------------------------
__global__ void dwgelu_kernel(const float* __restrict__ w, const float* __restrict__ b) {
    __shared__ float s[66 * 66];
    const int c = blockIdx.x;
    const int tid = threadIdx.x;
    const float* in = g_buf + OFF_Y1 + (c << 12);
    for (int i = tid; i < 66 * 66; i += 256) {
        int yy = i / 66, xx = i - yy * 66;
        int gy = yy - 1, gx = xx - 1;
        float v = 0.f;
        if ((unsigned)gy < 64u && (unsigned)gx < 64u) v = in[gy * 64 + gx];
        s[i] = v;
    }
    __syncthreads();
    float wv[9];
#pragma unroll
    for (int k = 0; k < 9; k++) wv[k] = w[c * 9 + k];
    float bb = b[c];
#pragma unroll 4
    for (int t = 0; t < 16; t++) {
        int n = tid + t * 256;
        int y = n >> 6, x = n & 63;
        float a = bb;
#pragma unroll
        for (int ky = 0; ky < 3; ky++)
#pragma unroll
            for (int kx = 0; kx < 3; kx++)
                a = fmaf(wv[ky * 3 + kx], s[(y + ky) * 66 + x + kx], a);
        g_buf[OFF_Y2 + (c << 12) + n] = 0.5f * a * (1.0f + erff(a * 0.7071067811865476f));
    }
}

// ---------------------------------------------------------------------------
// Launch
// ---------------------------------------------------------------------------
extern "C" void kernel_launch(void* const* d_in, const int* in_sizes, int n_in,
                              void* d_out, int out_size) {
    const float* x      = (const float*)d_in[0];
    const float* luma   = (const float*)d_in[1];
    const float* ln1_w  = (const float*)d_in[2];
    const float* ln1_b  = (const float*)d_in[3];
    const float* qkv_w  = (const float*)d_in[4];
    const float* qkv_b  = (const float*)d_in[5];
    const float* proj_w = (const float*)d_in[6];
    const float* proj_b = (const float*)d_in[7];
    const float* lc1_w  = (const float*)d_in[8];
    const float* lc1_b  = (const float*)d_in[9];
    const float* lc2_w  = (const float*)d_in[10];
    const float* lc2_b  = (const float*)d_in[11];
    const float* gam_w  = (const float*)d_in[12];
    const float* gam_b  = (const float*)d_in[13];
    const float* bet_w  = (const float*)d_in[14];
    const float* bet_b  = (const float*)d_in[15];
    const float* alpha  = (const float*)d_in[16];
    const float* ln2_w  = (const float*)d_in[17];
    const float* ln2_b  = (const float*)d_in[18];
    const float* ffn1_w = (const float*)d_in[19];
    const float* ffn1_b = (const float*)d_in[20];
    const float* dw_w   = (const float*)d_in[21];
    const float* dw_b   = (const float*)d_in[22];
    const float* ffn2_w = (const float*)d_in[23];
    const float* ffn2_b = (const float*)d_in[24];
    float* out = (float*)d_out;

    float* buf = nullptr;
    cudaGetSymbolAddress((void**)&buf, g_buf);

    // --- attention branch ---
    ln_kernel<<<16, 256>>>(x, ln1_w, ln1_b, buf + OFF_XN);
    gemm16_kernel<64><<<dim3(16, 12), 256>>>(qkv_w, qkv_b, buf + OFF_XN, buf + OFF_QKV, nullptr);
    lc1_kernel<<<512, 256>>>(luma, lc1_w, lc1_b);
    lc2_tiled_kernel<<<128, 256>>>(lc2_w, lc2_b);
    gemm16_kernel<32><<<dim3(16, 4), 256>>>(gam_w, gam_b, buf + OFF_H2, buf + OFF_GAM, nullptr);
    gemm16_kernel<32><<<dim3(16, 4), 256>>>(bet_w, bet_b, buf + OFF_H2, buf + OFF_BET, nullptr);
    pool_mean_kernel<<<1, 1024>>>(luma);
    modulate_kernel<<<3072, 256>>>(alpha);
    knorm_kernel<<<8, 256>>>();
    attn_kernel<<<dim3(8, 8, 4), 128>>>();
    combine_kernel<<<128, 256>>>();
    gemm16_kernel<64><<<dim3(16, 4), 256>>>(proj_w, proj_b, buf + OFF_AO, buf + OFF_X2, x);

    // --- ConvFFN branch ---
    ln_kernel<<<16, 256>>>(buf + OFF_X2, ln2_w, ln2_b, buf + OFF_YN);
    gemm16_kernel<64><<<dim3(16, 16), 256>>>(ffn1_w, ffn1_b, buf + OFF_YN, buf + OFF_Y1, nullptr);
    dwgelu_kernel<<<256, 256>>>(dw_w, dw_b);
    gemm16_kernel<256><<<dim3(16, 4), 256>>>(ffn2_w, ffn2_b, buf + OFF_Y2, out, buf + OFF_X2);
}

// round 3
// speedup vs baseline: 1.5735x; 1.0658x over previous
#include <cuda_runtime.h>
#include <cuda_bf16.h>
#include <math.h>

// ---------------------------------------------------------------------------
// B=1, C=64, H=W=64, N=4096, heads=8, dh=8, inner=64, hid_lc=32, hid_f=256.
// Activations fp32, [channel][pixel] layout.
// ---------------------------------------------------------------------------

constexpr int NPIX = 4096;

constexpr int OFF_QKV  = 0;                        // 192*N
constexpr int OFF_QKVM = OFF_QKV  + 192 * NPIX;    // 192*N
constexpr int OFF_H2   = OFF_QKVM + 192 * NPIX;    // 32*N
constexpr int OFF_GAM  = OFF_H2   + 32  * NPIX;    // 64*N
constexpr int OFF_BET  = OFF_GAM  + 64  * NPIX;    // 64*N
constexpr int OFF_INVL = OFF_BET  + 64  * NPIX;    // N
constexpr int OFF_MEAN = OFF_INVL + NPIX;          // [0]=mean
constexpr int OFF_KN   = OFF_MEAN + 8;             // [0..7] max||k||^2 per head
constexpr int OFF_PL   = OFF_MEAN + 64;            // 8 splits * 8 heads * N
constexpr int OFF_PACC = OFF_PL   + 64 * NPIX;     // 8 splits * 64 ch * N
constexpr int OFF_X2   = OFF_PACC + 512 * NPIX;    // 64*N
constexpr int OFF_Y1   = OFF_X2   + 64  * NPIX;    // 256*N
constexpr int OFF_Y2   = OFF_Y1   + 256 * NPIX;    // 256*N
constexpr int TOTAL_F  = OFF_Y2   + 256 * NPIX;

__device__ float g_buf[TOTAL_F];

// ---------------- packed f32x2 helpers --------------------------------------
typedef unsigned long long u64;
__device__ __forceinline__ u64 pack2(float lo, float hi) {
    u64 r; asm("mov.b64 %0,{%1,%2};" : "=l"(r) : "f"(lo), "f"(hi)); return r;
}
__device__ __forceinline__ float2 unpack2(u64 v) {
    float2 r; asm("mov.b64 {%0,%1},%2;" : "=f"(r.x), "=f"(r.y) : "l"(v)); return r;
}
__device__ __forceinline__ u64 fma2(u64 a, u64 b, u64 c) {
    u64 d; asm("fma.rn.f32x2 %0,%1,%2,%3;" : "=l"(d) : "l"(a), "l"(b), "l"(c)); return d;
}
__device__ __forceinline__ u64 mul2(u64 a, u64 b) {
    u64 d; asm("mul.rn.f32x2 %0,%1,%2;" : "=l"(d) : "l"(a), "l"(b)); return d;
}
__device__ __forceinline__ float ex2f(float x) {
    float y; asm("ex2.approx.f32 %0,%1;" : "=f"(y) : "f"(x)); return y;
}

// ---------------------------------------------------------------------------
// Fused per-pixel LayerNorm + 1x1-conv GEMM (K=64), 16 output rows per CTA.
// Each thread owns one pixel: loads 64 channels to registers, computes LN,
// then runs the K-loop entirely from registers (no LDS for activations).
// ---------------------------------------------------------------------------
__global__ void __launch_bounds__(256) ln_gemm_kernel(
        const float* __restrict__ x, const float* __restrict__ lnw,
        const float* __restrict__ lnb, const float* __restrict__ W,
        const float* __restrict__ bias, float* __restrict__ Y) {
    __shared__ u64 ws2[8 * 64];
    __shared__ float wl[64], bl[64];
    const int row0 = blockIdx.y * 16;
    for (int i = threadIdx.x; i < 512; i += 256) {
        int p = i >> 6, k = i & 63;
        ws2[i] = pack2(W[(row0 + 2 * p) * 64 + k], W[(row0 + 2 * p + 1) * 64 + k]);
    }
    if (threadIdx.x < 64) { wl[threadIdx.x] = lnw[threadIdx.x]; bl[threadIdx.x] = lnb[threadIdx.x]; }
    __syncthreads();
    const int n = blockIdx.x * 256 + threadIdx.x;
    float v[64];
    float s = 0.f;
#pragma unroll
    for (int c = 0; c < 64; c++) { v[c] = x[(c << 12) + n]; s += v[c]; }
    float mu = s * (1.f / 64.f);
    float ss = 0.f;
#pragma unroll
    for (int c = 0; c < 64; c++) { float d = v[c] - mu; ss = fmaf(d, d, ss); }
    float rs = rsqrtf(ss * (1.f / 64.f) + 1e-5f);
#pragma unroll
    for (int c = 0; c < 64; c++) v[c] = (v[c] - mu) * rs * wl[c] + bl[c];

    u64 acc[8];
#pragma unroll
    for (int p = 0; p < 8; p++) acc[p] = 0ULL;
#pragma unroll 8
    for (int k = 0; k < 64; k++) {
        u64 x2 = pack2(v[k], v[k]);
#pragma unroll
        for (int p = 0; p < 8; p++) acc[p] = fma2(ws2[p * 64 + k], x2, acc[p]);
    }
#pragma unroll
    for (int p = 0; p < 8; p++) {
        float2 a = unpack2(acc[p]);
        int r0 = row0 + 2 * p;
        Y[(r0 << 12) + n] = a.x + bias[r0];
        Y[((r0 + 1) << 12) + n] = a.y + bias[r0 + 1];
    }
}

// ---------------------------------------------------------------------------
// Fused lc1 (1->32, 3x3, relu) + lc2 (32->32, 3x3, relu).
// Grid 128 = 64 spatial 8x8 tiles x 2 oc-halves. lc1 computed into smem with
// a 1-pixel halo (10x10 region); lc2 consumes it from smem; H1 never in gmem.
// ---------------------------------------------------------------------------
__global__ void __launch_bounds__(256) lc_fused_kernel(
        const float* __restrict__ luma,
        const float* __restrict__ w1, const float* __restrict__ b1,
        const float* __restrict__ w2, const float* __restrict__ b2) {
    __shared__ float lum[12][13];
    __shared__ float wl1[32][9];
    __shared__ float h1s[32][10][12];
    __shared__ float ws[16][32][9];
    const int bx = blockIdx.x;
    const int tile = bx >> 1, oh = bx & 1;
    const int ty0 = (tile >> 3) * 8, tx0 = (tile & 7) * 8;
    const int tid = threadIdx.x;

    for (int i = tid; i < 144; i += 256) {
        int yy = i / 12, xx = i - yy * 12;
        int gy = ty0 + yy - 2, gx = tx0 + xx - 2;
        float v = 0.f;
        if ((unsigned)gy < 64u && (unsigned)gx < 64u) v = luma[gy * 64 + gx];
        lum[yy][xx] = v;
    }
    for (int i = tid; i < 288; i += 256) wl1[i / 9][i % 9] = w1[i];
    for (int i = tid; i < 16 * 32 * 9; i += 256) {
        int ocl = i / 288, r = i - ocl * 288;
        ws[ocl][r / 9][r % 9] = w2[(oh * 16 + ocl) * 288 + r];
    }
    __syncthreads();

    // lc1 into smem: 10x10 region (tile + halo), 32 channels
    for (int i = tid; i < 3200; i += 256) {
        int ic = i / 100, r = i - ic * 100;
        int yy = r / 10, xx = r - yy * 10;
        int gy = ty0 + yy - 1, gx = tx0 + xx - 1;
        float v = 0.f;
        if ((unsigned)gy < 64u && (unsigned)gx < 64u) {
            float a = b1[ic];
#pragma unroll
            for (int ky = 0; ky < 3; ky++)
#pragma unroll
                for (int kx = 0; kx < 3; kx++)
                    a = fmaf(wl1[ic][ky * 3 + kx], lum[yy + ky][xx + kx], a);
            v = fmaxf(a, 0.f);
        }
        h1s[ic][yy][xx] = v;
    }
    __syncthreads();

    // lc2: thread = (ocl 0..15, pixel-quad 0..15)
    const int ocl = tid >> 4, pg = tid & 15;
    const int py = pg >> 1, px = (pg & 1) * 4;
    const int oc = oh * 16 + ocl;
    float acc[4];
    float bb = b2[oc];
#pragma unroll
    for (int o = 0; o < 4; o++) acc[o] = bb;

    for (int ic = 0; ic < 32; ic++) {
        const float* base = &h1s[ic][py][0];
        float c[3][6];
#pragma unroll
        for (int r = 0; r < 3; r++)
#pragma unroll
            for (int q = 0; q < 6; q++) c[r][q] = base[r * 12 + px + q];
        const float* wr = &ws[ocl][ic][0];
#pragma unroll
        for (int ky = 0; ky < 3; ky++)
#pragma unroll
            for (int kx = 0; kx < 3; kx++) {
                float wv = wr[ky * 3 + kx];
#pragma unroll
                for (int o = 0; o < 4; o++) acc[o] = fmaf(wv, c[ky][kx + o], acc[o]);
            }
    }
    int gy = ty0 + py, gx = tx0 + px;
#pragma unroll
    for (int o = 0; o < 4; o++)
        g_buf[OFF_H2 + (oc << 12) + gy * 64 + gx + o] = fmaxf(acc[o], 0.f);
}

// ---------------------------------------------------------------------------
// gamma/beta GEMMs (K=32) + pool/mean, one launch. Grid (16, 9):
//   by 0..3 -> gamma rows, by 4..7 -> beta rows, by==8 (bx==0) -> pool+mean.
// ---------------------------------------------------------------------------
__global__ void __launch_bounds__(256) gambet_pool_kernel(
        const float* __restrict__ gw, const float* __restrict__ gb,
        const float* __restrict__ bw, const float* __restrict__ bb,
        const float* __restrict__ luma) {
    const int by = blockIdx.y, tid = threadIdx.x;
    if (by == 8) {
        if (blockIdx.x != 0) return;
        __shared__ float sm[256];
        float tot = 0.f;
        for (int q = 0; q < 16; q++) {
            int n = tid + q * 256;
            int y = n >> 6, x = n & 63;
            float s = 0.f;
#pragma unroll
            for (int dy = -1; dy <= 1; dy++) {
                int iy = y + dy;
                if ((unsigned)iy < 64u) {
#pragma unroll
                    for (int dx = -1; dx <= 1; dx++) {
                        int ix = x + dx;
                        if ((unsigned)ix < 64u) s += 1.0f - luma[iy * 64 + ix];
                    }
                }
            }
            s *= (1.0f / 9.0f);
            g_buf[OFF_INVL + n] = s;
            tot += s;
        }
        sm[tid] = tot;
        __syncthreads();
        for (int st = 128; st > 0; st >>= 1) {
            if (tid < st) sm[tid] += sm[tid + st];
            __syncthreads();
        }
        if (tid == 0) g_buf[OFF_MEAN] = sm[0] * (1.0f / 4096.0f);
        return;
    }
    const bool isg = by < 4;
    const float* W = isg ? gw : bw;
    const float* bias = isg ? gb : bb;
    const int outoff = isg ? OFF_GAM : OFF_BET;
    const int row0 = (by & 3) * 16;
    __shared__ u64 ws2[8 * 32];
    for (int i = tid; i < 256; i += 256) {
        int p = i >> 5, k = i & 31;
        ws2[i] = pack2(W[(row0 + 2 * p) * 32 + k], W[(row0 + 2 * p + 1) * 32 + k]);
    }
    __syncthreads();
    const int n = blockIdx.x * 256 + tid;
    u64 acc[8];
#pragma unroll
    for (int p = 0; p < 8; p++) acc[p] = 0ULL;
#pragma unroll 8
    for (int k = 0; k < 32; k++) {
        float xv = g_buf[OFF_H2 + (k << 12) + n];
        u64 x2 = pack2(xv, xv);
#pragma unroll
        for (int p = 0; p < 8; p++) acc[p] = fma2(ws2[p * 32 + k], x2, acc[p]);
    }
#pragma unroll
    for (int p = 0; p < 8; p++) {
        float2 a = unpack2(acc[p]);
        int r0 = row0 + 2 * p;
        g_buf[outoff + (r0 << 12) + n] = a.x + bias[r0];
        g_buf[outoff + ((r0 + 1) << 12) + n] = a.y + bias[r0 + 1];
    }
}

// ---------------------------------------------------------------------------
// Modulation of q,k,v + alpha luma bias on q.
// ---------------------------------------------------------------------------
__global__ void modulate_kernel(const float* __restrict__ alpha_p) {
    int idx = blockIdx.x * 256 + threadIdx.x;      // 192*4096
    int c = idx >> 12, n = idx & 4095;
    int cg = c & 63;
    float g = g_buf[OFF_GAM + (cg << 12) + n];
    float bt = g_buf[OFF_BET + (cg << 12) + n];
    float v = fmaf(g, g_buf[OFF_QKV + idx], bt);
    if (c < 64) v = fmaf(alpha_p[0], g_buf[OFF_INVL + n] - g_buf[OFF_MEAN], v);
    g_buf[OFF_QKVM + idx] = v;
}

// ---------------------------------------------------------------------------
// Per-head max ||k||^2 (Cauchy-Schwarz softmax bound).
// ---------------------------------------------------------------------------
__global__ void knorm_kernel() {
    __shared__ float sm[256];
    int h = blockIdx.x, tid = threadIdx.x;
    const float* kp = g_buf + OFF_QKVM + (64 + h * 8) * NPIX;
    float mx = 0.f;
    for (int j = tid; j < NPIX; j += 256) {
        float ss = 0.f;
#pragma unroll
        for (int d = 0; d < 8; d++) { float v = kp[(d << 12) + j]; ss = fmaf(v, v, ss); }
        mx = fmaxf(mx, ss);
    }
    sm[tid] = mx;
    __syncthreads();
    for (int st = 128; st > 0; st >>= 1) {
        if (tid < st) sm[tid] = fmaxf(sm[tid], sm[tid + st]);
        __syncthreads();
    }
    if (tid == 0) g_buf[OFF_KN + h] = sm[0];
}

// ---------------------------------------------------------------------------
// Flash attention, packed f32x2, branch-free bounded softmax, 8 key-splits.
// Grid (4 qblk, 8 heads, 8 ksplit) = 256 CTAs, 128 thr, 8 queries/thread.
// ---------------------------------------------------------------------------
__global__ void __launch_bounds__(128, 1) attn_kernel() {
    __shared__ __align__(16) float ks[4096];   // [j][d] 512x8
    __shared__ __align__(16) float vs[4096];
    const int h = blockIdx.y, z = blockIdx.z;
    const int n0 = blockIdx.x * 1024;
    const int tid = threadIdx.x;
    const float* qp = g_buf + OFF_QKVM + (h * 8) * NPIX;
    const float* kp = g_buf + OFF_QKVM + (64 + h * 8) * NPIX;
    const float* vp = g_buf + OFF_QKVM + (128 + h * 8) * NPIX;
    const float kn2 = g_buf[OFF_KN + h];
    const float sc = 0.35355339059327373f * 1.4426950408889634f;  // dh^-0.5 * log2(e)

    u64 q2[8][4], acc2[8][4];
    float M[8], l[8];
#pragma unroll
    for (int i = 0; i < 8; i++) {
        int n = n0 + tid + i * 128;
        float qv[8], qn2 = 0.f;
#pragma unroll
        for (int d = 0; d < 8; d++) { qv[d] = qp[(d << 12) + n] * sc; qn2 = fmaf(qv[d], qv[d], qn2); }
        M[i] = sqrtf(qn2 * kn2);   // >= any score; identical across splits
        l[i] = 0.f;
        q2[i][0] = pack2(qv[0], qv[1]); q2[i][1] = pack2(qv[2], qv[3]);
        q2[i][2] = pack2(qv[4], qv[5]); q2[i][3] = pack2(qv[6], qv[7]);
#pragma unroll
        for (int p = 0; p < 4; p++) acc2[i][p] = 0ULL;
    }

    const int jt = z * 512;
    for (int i2 = tid; i2 < 4096; i2 += 128) {
        int d = i2 >> 9, j = i2 & 511;
        ks[j * 8 + d] = kp[(d << 12) + jt + j];
        vs[j * 8 + d] = vp[(d << 12) + jt + j];
    }
    __syncthreads();

    const ulonglong2* k2p = (const ulonglong2*)ks;
    const ulonglong2* v2p = (const ulonglong2*)vs;
    ulonglong2 ka = k2p[0], kb = k2p[1], va = v2p[0], vb = v2p[1];
    for (int j = 0; j < 512; j++) {
        int jn = (j + 1) & 511;
        ulonglong2 nka = k2p[jn * 2], nkb = k2p[jn * 2 + 1];
        ulonglong2 nva = v2p[jn * 2], nvb = v2p[jn * 2 + 1];
#pragma unroll
        for (int i = 0; i < 8; i++) {
            u64 s2 = fma2(q2[i][0], ka.x,
                     fma2(q2[i][1], ka.y,
                     fma2(q2[i][2], kb.x,
                     mul2(q2[i][3], kb.y))));
            float2 sf = unpack2(s2);
            float p = ex2f(sf.x + sf.y - M[i]);
            l[i] += p;
            u64 p2 = pack2(p, p);
            acc2[i][0] = fma2(p2, va.x, acc2[i][0]);
            acc2[i][1] = fma2(p2, va.y, acc2[i][1]);
            acc2[i][2] = fma2(p2, vb.x, acc2[i][2]);
            acc2[i][3] = fma2(p2, vb.y, acc2[i][3]);
        }
        ka = nka; kb = nkb; va = nva; vb = nvb;
    }

    float* pl = g_buf + OFF_PL;
    float* pacc = g_buf + OFF_PACC;
#pragma unroll
    for (int i = 0; i < 8; i++) {
        int n = n0 + tid + i * 128;
        pl[((z * 8 + h) << 12) + n] = l[i];
#pragma unroll
        for (int p = 0; p < 4; p++) {
            float2 a = unpack2(acc2[i][p]);
            pacc[((z * 64 + h * 8 + 2 * p) << 12) + n] = a.x;
            pacc[((z * 64 + h * 8 + 2 * p + 1) << 12) + n] = a.y;
        }
    }
}

// ---------------------------------------------------------------------------
// Fused split-combine + projection GEMM (K=64) + residual. Grid (16, 2),
// 32 output rows per CTA; combine result held in registers.
// ---------------------------------------------------------------------------
__global__ void __launch_bounds__(256) combineproj_kernel(
        const float* __restrict__ W, const float* __restrict__ bias,
        const float* __restrict__ xres) {
    __shared__ u64 ws2[16 * 64];
    const int row0 = blockIdx.y * 32;
    for (int i = threadIdx.x; i < 1024; i += 256) {
        int p = i >> 6, k = i & 63;
        ws2[i] = pack2(W[(row0 + 2 * p) * 64 + k], W[(row0 + 2 * p + 1) * 64 + k]);
    }
    __syncthreads();
    const int n = blockIdx.x * 256 + threadIdx.x;
    const float* pl = g_buf + OFF_PL;
    const float* pacc = g_buf + OFF_PACC;
    float a[64];
#pragma unroll
    for (int h = 0; h < 8; h++) {
        float L = 1e-35f;
#pragma unroll
        for (int s = 0; s < 8; s++) L += pl[((s * 8 + h) << 12) + n];
        float rL = 1.0f / L;
#pragma unroll
        for (int d = 0; d < 8; d++) {
            float o = 0.f;
#pragma unroll
            for (int s = 0; s < 8; s++) o += pacc[((s * 64 + h * 8 + d) << 12) + n];
            a[h * 8 + d] = o * rL;
        }
    }
    u64 acc[16];
#pragma unroll
    for (int p = 0; p < 16; p++) acc[p] = 0ULL;
#pragma unroll 8
    for (int k = 0; k < 64; k++) {
        u64 x2 = pack2(a[k], a[k]);
#pragma unroll
        for (int p = 0; p < 16; p++) acc[p] = fma2(ws2[p * 64 + k], x2, acc[p]);
    }
#pragma unroll
    for (int p = 0; p < 16; p++) {
        float2 v = unpack2(acc[p]);
        int r0 = row0 + 2 * p;
        g_buf[OFF_X2 + (r0 << 12) + n] = v.x + bias[r0] + xres[(r0 << 12) + n];
        g_buf[OFF_X2 + ((r0 + 1) << 12) + n] = v.y + bias[r0 + 1] + xres[((r0 + 1) << 12) + n];
    }
}

// ---------------------------------------------------------------------------
// Depthwise 3x3 conv + exact GELU, one CTA per channel, smem halo tile.
// ---------------------------------------------------------------------------
__global__ void __launch_bounds__(256) dwgelu_kernel(const float* __restrict__ w,
                                                     const float* __restrict__ b) {
    __shared__ float s[66 * 66];
    const int c = blockIdx.x;
    const int tid = threadIdx.x;
    const float* in = g_buf + OFF_Y1 + (c << 12);
    for (int i = tid; i < 66 * 66; i += 256) {
        int yy = i / 66, xx = i - yy * 66;
        int gy = yy - 1, gx = xx - 1;
        float v = 0.f;
        if ((unsigned)gy < 64u && (unsigned)gx < 64u) v = in[gy * 64 + gx];
        s[i] = v;
    }
    __syncthreads();
    float wv[9];
#pragma unroll
    for (int k = 0; k < 9; k++) wv[k] = w[c * 9 + k];
    float bb = b[c];
#pragma unroll 4
    for (int t = 0; t < 16; t++) {
        int n = tid + t * 256;
        int y = n >> 6, x = n & 63;
        float a = bb;
#pragma unroll
        for (int ky = 0; ky < 3; ky++)
#pragma unroll
            for (int kx = 0; kx < 3; kx++)
                a = fmaf(wv[ky * 3 + kx], s[(y + ky) * 66 + x + kx], a);
        g_buf[OFF_Y2 + (c << 12) + n] = 0.5f * a * (1.0f + erff(a * 0.7071067811865476f));
    }
}

// ---------------------------------------------------------------------------
// ffn2: 1x1 conv GEMM K=256 + residual (writes final output).
// ---------------------------------------------------------------------------
__global__ void __launch_bounds__(256) ffn2_kernel(const float* __restrict__ W,
                                                   const float* __restrict__ bias,
                                                   float* __restrict__ Y) {
    __shared__ u64 ws2[8 * 256];
    const int row0 = blockIdx.y * 16;
    for (int i = threadIdx.x; i < 2048; i += 256) {
        int p = i >> 8, k = i & 255;
        ws2[i] = pack2(W[(row0 + 2 * p) * 256 + k], W[(row0 + 2 * p + 1) * 256 + k]);
    }
    __syncthreads();
    const int n = blockIdx.x * 256 + threadIdx.x;
    u64 acc[8];
#pragma unroll
    for (int p = 0; p < 8; p++) acc[p] = 0ULL;
#pragma unroll 8
    for (int k = 0; k < 256; k++) {
        float xv = g_buf[OFF_Y2 + (k << 12) + n];
        u64 x2 = pack2(xv, xv);
#pragma unroll
        for (int p = 0; p < 8; p++) acc[p] = fma2(ws2[p * 256 + k], x2, acc[p]);
    }
#pragma unroll
    for (int p = 0; p < 8; p++) {
        float2 a = unpack2(acc[p]);
        int r0 = row0 + 2 * p;
        Y[(r0 << 12) + n] = a.x + bias[r0] + g_buf[OFF_X2 + (r0 << 12) + n];
        Y[((r0 + 1) << 12) + n] = a.y + bias[r0 + 1] + g_buf[OFF_X2 + ((r0 + 1) << 12) + n];
    }
}

// ---------------------------------------------------------------------------
// Launch
// ---------------------------------------------------------------------------
extern "C" void kernel_launch(void* const* d_in, const int* in_sizes, int n_in,
                              void* d_out, int out_size) {
    const float* x      = (const float*)d_in[0];
    const float* luma   = (const float*)d_in[1];
    const float* ln1_w  = (const float*)d_in[2];
    const float* ln1_b  = (const float*)d_in[3];
    const float* qkv_w  = (const float*)d_in[4];
    const float* qkv_b  = (const float*)d_in[5];
    const float* proj_w = (const float*)d_in[6];
    const float* proj_b = (const float*)d_in[7];
    const float* lc1_w  = (const float*)d_in[8];
    const float* lc1_b  = (const float*)d_in[9];
    const float* lc2_w  = (const float*)d_in[10];
    const float* lc2_b  = (const float*)d_in[11];
    const float* gam_w  = (const float*)d_in[12];
    const float* gam_b  = (const float*)d_in[13];
    const float* bet_w  = (const float*)d_in[14];
    const float* bet_b  = (const float*)d_in[15];
    const float* alpha  = (const float*)d_in[16];
    const float* ln2_w  = (const float*)d_in[17];
    const float* ln2_b  = (const float*)d_in[18];
    const float* ffn1_w = (const float*)d_in[19];
    const float* ffn1_b = (const float*)d_in[20];
    const float* dw_w   = (const float*)d_in[21];
    const float* dw_b   = (const float*)d_in[22];
    const float* ffn2_w = (const float*)d_in[23];
    const float* ffn2_b = (const float*)d_in[24];
    float* out = (float*)d_out;

    float* buf = nullptr;
    cudaGetSymbolAddress((void**)&buf, g_buf);

    ln_gemm_kernel<<<dim3(16, 12), 256>>>(x, ln1_w, ln1_b, qkv_w, qkv_b, buf + OFF_QKV);
    lc_fused_kernel<<<128, 256>>>(luma, lc1_w, lc1_b, lc2_w, lc2_b);
    gambet_pool_kernel<<<dim3(16, 9), 256>>>(gam_w, gam_b, bet_w, bet_b, luma);
    modulate_kernel<<<3072, 256>>>(alpha);
    knorm_kernel<<<8, 256>>>();
    attn_kernel<<<dim3(4, 8, 8), 128>>>();
    combineproj_kernel<<<dim3(16, 2), 256>>>(proj_w, proj_b, x);
    ln_gemm_kernel<<<dim3(16, 16), 256>>>(buf + OFF_X2, ln2_w, ln2_b, ffn1_w, ffn1_b, buf + OFF_Y1);
    dwgelu_kernel<<<256, 256>>>(dw_w, dw_b);
    ffn2_kernel<<<dim3(16, 4), 256>>>(ffn2_w, ffn2_b, out);
}

// round 4
// speedup vs baseline: 1.6417x; 1.0434x over previous
#include <cuda_runtime.h>
#include <cuda_bf16.h>
#include <math.h>

// ---------------------------------------------------------------------------
// B=1, C=64, H=W=64, N=4096, heads=8, dh=8, inner=64, hid_lc=32, hid_f=256.
// Activations fp32, [channel][pixel] layout.
// ---------------------------------------------------------------------------

constexpr int NPIX = 4096;

constexpr int OFF_QKV  = 0;                        // 192*N
constexpr int OFF_QKVM = OFF_QKV  + 192 * NPIX;    // 192*N
constexpr int OFF_H2   = OFF_QKVM + 192 * NPIX;    // 32*N
constexpr int OFF_GAM  = OFF_H2   + 32  * NPIX;    // 64*N
constexpr int OFF_BET  = OFF_GAM  + 64  * NPIX;    // 64*N
constexpr int OFF_INVL = OFF_BET  + 64  * NPIX;    // N
constexpr int OFF_MEAN = OFF_INVL + NPIX;          // [0]=mean
constexpr int OFF_KN   = OFF_MEAN + 8;             // [0..7] max||k||^2 per head
constexpr int OFF_PL   = OFF_MEAN + 64;            // 8 splits * 8 heads * N
constexpr int OFF_PACC = OFF_PL   + 64 * NPIX;     // 8 splits * 64 ch * N
constexpr int OFF_X2   = OFF_PACC + 512 * NPIX;    // 64*N
constexpr int OFF_Y1   = OFF_X2   + 64  * NPIX;    // 256*N
constexpr int OFF_Y2   = OFF_Y1   + 256 * NPIX;    // 256*N
constexpr int TOTAL_F  = OFF_Y2   + 256 * NPIX;

__device__ float g_buf[TOTAL_F];

// ---------------- packed f32x2 helpers --------------------------------------
typedef unsigned long long u64;
__device__ __forceinline__ u64 pack2(float lo, float hi) {
    u64 r; asm("mov.b64 %0,{%1,%2};" : "=l"(r) : "f"(lo), "f"(hi)); return r;
}
__device__ __forceinline__ float2 unpack2(u64 v) {
    float2 r; asm("mov.b64 {%0,%1},%2;" : "=f"(r.x), "=f"(r.y) : "l"(v)); return r;
}
__device__ __forceinline__ u64 fma2(u64 a, u64 b, u64 c) {
    u64 d; asm("fma.rn.f32x2 %0,%1,%2,%3;" : "=l"(d) : "l"(a), "l"(b), "l"(c)); return d;
}
__device__ __forceinline__ u64 add2(u64 a, u64 b) {
    u64 d; asm("add.rn.f32x2 %0,%1,%2;" : "=l"(d) : "l"(a), "l"(b)); return d;
}
__device__ __forceinline__ u64 mul2(u64 a, u64 b) {
    u64 d; asm("mul.rn.f32x2 %0,%1,%2;" : "=l"(d) : "l"(a), "l"(b)); return d;
}
__device__ __forceinline__ float ex2f(float x) {
    float y; asm("ex2.approx.f32 %0,%1;" : "=f"(y) : "f"(x)); return y;
}

// ---------------------------------------------------------------------------
// Fused per-pixel LayerNorm + 1x1-conv GEMM (K=64), 16 output rows per CTA.
// ---------------------------------------------------------------------------
__global__ void __launch_bounds__(256) ln_gemm_kernel(
        const float* __restrict__ x, const float* __restrict__ lnw,
        const float* __restrict__ lnb, const float* __restrict__ W,
        const float* __restrict__ bias, float* __restrict__ Y) {
    __shared__ u64 ws2[8 * 64];
    __shared__ float wl[64], bl[64];
    const int row0 = blockIdx.y * 16;
    for (int i = threadIdx.x; i < 512; i += 256) {
        int p = i >> 6, k = i & 63;
        ws2[i] = pack2(W[(row0 + 2 * p) * 64 + k], W[(row0 + 2 * p + 1) * 64 + k]);
    }
    if (threadIdx.x < 64) { wl[threadIdx.x] = lnw[threadIdx.x]; bl[threadIdx.x] = lnb[threadIdx.x]; }
    __syncthreads();
    const int n = blockIdx.x * 256 + threadIdx.x;
    float v[64];
    float s = 0.f;
#pragma unroll
    for (int c = 0; c < 64; c++) { v[c] = x[(c << 12) + n]; s += v[c]; }
    float mu = s * (1.f / 64.f);
    float ss = 0.f;
#pragma unroll
    for (int c = 0; c < 64; c++) { float d = v[c] - mu; ss = fmaf(d, d, ss); }
    float rs = rsqrtf(ss * (1.f / 64.f) + 1e-5f);
#pragma unroll
    for (int c = 0; c < 64; c++) v[c] = (v[c] - mu) * rs * wl[c] + bl[c];

    u64 acc[8];
#pragma unroll
    for (int p = 0; p < 8; p++) acc[p] = 0ULL;
#pragma unroll 8
    for (int k = 0; k < 64; k++) {
        u64 x2 = pack2(v[k], v[k]);
#pragma unroll
        for (int p = 0; p < 8; p++) acc[p] = fma2(ws2[p * 64 + k], x2, acc[p]);
    }
#pragma unroll
    for (int p = 0; p < 8; p++) {
        float2 a = unpack2(acc[p]);
        int r0 = row0 + 2 * p;
        Y[(r0 << 12) + n] = a.x + bias[r0];
        Y[((r0 + 1) << 12) + n] = a.y + bias[r0 + 1];
    }
}

// ---------------------------------------------------------------------------
// Fused lc1 (1->32, 3x3, relu) + lc2 (32->32, 3x3, relu).
// ---------------------------------------------------------------------------
__global__ void __launch_bounds__(256) lc_fused_kernel(
        const float* __restrict__ luma,
        const float* __restrict__ w1, const float* __restrict__ b1,
        const float* __restrict__ w2, const float* __restrict__ b2) {
    __shared__ float lum[12][13];
    __shared__ float wl1[32][9];
    __shared__ float h1s[32][10][12];
    __shared__ float ws[16][32][9];
    const int bx = blockIdx.x;
    const int tile = bx >> 1, oh = bx & 1;
    const int ty0 = (tile >> 3) * 8, tx0 = (tile & 7) * 8;
    const int tid = threadIdx.x;

    for (int i = tid; i < 144; i += 256) {
        int yy = i / 12, xx = i - yy * 12;
        int gy = ty0 + yy - 2, gx = tx0 + xx - 2;
        float v = 0.f;
        if ((unsigned)gy < 64u && (unsigned)gx < 64u) v = luma[gy * 64 + gx];
        lum[yy][xx] = v;
    }
    for (int i = tid; i < 288; i += 256) wl1[i / 9][i % 9] = w1[i];
    for (int i = tid; i < 16 * 32 * 9; i += 256) {
        int ocl = i / 288, r = i - ocl * 288;
        ws[ocl][r / 9][r % 9] = w2[(oh * 16 + ocl) * 288 + r];
    }
    __syncthreads();

    for (int i = tid; i < 3200; i += 256) {
        int ic = i / 100, r = i - ic * 100;
        int yy = r / 10, xx = r - yy * 10;
        int gy = ty0 + yy - 1, gx = tx0 + xx - 1;
        float v = 0.f;
        if ((unsigned)gy < 64u && (unsigned)gx < 64u) {
            float a = b1[ic];
#pragma unroll
            for (int ky = 0; ky < 3; ky++)
#pragma unroll
                for (int kx = 0; kx < 3; kx++)
                    a = fmaf(wl1[ic][ky * 3 + kx], lum[yy + ky][xx + kx], a);
            v = fmaxf(a, 0.f);
        }
        h1s[ic][yy][xx] = v;
    }
    __syncthreads();

    const int ocl = tid >> 4, pg = tid & 15;
    const int py = pg >> 1, px = (pg & 1) * 4;
    const int oc = oh * 16 + ocl;
    float acc[4];
    float bb = b2[oc];
#pragma unroll
    for (int o = 0; o < 4; o++) acc[o] = bb;

    for (int ic = 0; ic < 32; ic++) {
        const float* base = &h1s[ic][py][0];
        float c[3][6];
#pragma unroll
        for (int r = 0; r < 3; r++)
#pragma unroll
            for (int q = 0; q < 6; q++) c[r][q] = base[r * 12 + px + q];
        const float* wr = &ws[ocl][ic][0];
#pragma unroll
        for (int ky = 0; ky < 3; ky++)
#pragma unroll
            for (int kx = 0; kx < 3; kx++) {
                float wv = wr[ky * 3 + kx];
#pragma unroll
                for (int o = 0; o < 4; o++) acc[o] = fmaf(wv, c[ky][kx + o], acc[o]);
            }
    }
    int gy = ty0 + py, gx = tx0 + px;
#pragma unroll
    for (int o = 0; o < 4; o++)
        g_buf[OFF_H2 + (oc << 12) + gy * 64 + gx + o] = fmaxf(acc[o], 0.f);
}

// ---------------------------------------------------------------------------
// gamma/beta GEMMs (K=32) + pool/mean, one launch. Grid (16, 9).
// ---------------------------------------------------------------------------
__global__ void __launch_bounds__(256) gambet_pool_kernel(
        const float* __restrict__ gw, const float* __restrict__ gb,
        const float* __restrict__ bw, const float* __restrict__ bb,
        const float* __restrict__ luma) {
    const int by = blockIdx.y, tid = threadIdx.x;
    if (by == 8) {
        if (blockIdx.x != 0) return;
        __shared__ float sm[256];
        float tot = 0.f;
        for (int q = 0; q < 16; q++) {
            int n = tid + q * 256;
            int y = n >> 6, x = n & 63;
            float s = 0.f;
#pragma unroll
            for (int dy = -1; dy <= 1; dy++) {
                int iy = y + dy;
                if ((unsigned)iy < 64u) {
#pragma unroll
                    for (int dx = -1; dx <= 1; dx++) {
                        int ix = x + dx;
                        if ((unsigned)ix < 64u) s += 1.0f - luma[iy * 64 + ix];
                    }
                }
            }
            s *= (1.0f / 9.0f);
            g_buf[OFF_INVL + n] = s;
            tot += s;
        }
        sm[tid] = tot;
        __syncthreads();
        for (int st = 128; st > 0; st >>= 1) {
            if (tid < st) sm[tid] += sm[tid + st];
            __syncthreads();
        }
        if (tid == 0) g_buf[OFF_MEAN] = sm[0] * (1.0f / 4096.0f);
        return;
    }
    const bool isg = by < 4;
    const float* W = isg ? gw : bw;
    const float* bias = isg ? gb : bb;
    const int outoff = isg ? OFF_GAM : OFF_BET;
    const int row0 = (by & 3) * 16;
    __shared__ u64 ws2[8 * 32];
    for (int i = tid; i < 256; i += 256) {
        int p = i >> 5, k = i & 31;
        ws2[i] = pack2(W[(row0 + 2 * p) * 32 + k], W[(row0 + 2 * p + 1) * 32 + k]);
    }
    __syncthreads();
    const int n = blockIdx.x * 256 + tid;
    u64 acc[8];
#pragma unroll
    for (int p = 0; p < 8; p++) acc[p] = 0ULL;
#pragma unroll 8
    for (int k = 0; k < 32; k++) {
        float xv = g_buf[OFF_H2 + (k << 12) + n];
        u64 x2 = pack2(xv, xv);
#pragma unroll
        for (int p = 0; p < 8; p++) acc[p] = fma2(ws2[p * 32 + k], x2, acc[p]);
    }
#pragma unroll
    for (int p = 0; p < 8; p++) {
        float2 a = unpack2(acc[p]);
        int r0 = row0 + 2 * p;
        g_buf[outoff + (r0 << 12) + n] = a.x + bias[r0];
        g_buf[outoff + ((r0 + 1) << 12) + n] = a.y + bias[r0 + 1];
    }
}

// ---------------------------------------------------------------------------
// Fused modulation (q,k,v) + per-head max||k||^2. Grid (16 nblk, 8 heads).
// Thread = (h, n): modulates 8 dims of q,k,v, reduces ||k||^2, atomicMax.
// KN is monotone-stable across graph replays (same max every run).
// ---------------------------------------------------------------------------
__global__ void __launch_bounds__(256) modknorm_kernel(const float* __restrict__ alpha_p) {
    __shared__ float sm[256];
    const int h = blockIdx.y;
    const int n = blockIdx.x * 256 + threadIdx.x;
    const float qb = alpha_p[0] * (g_buf[OFF_INVL + n] - g_buf[OFF_MEAN]);
    float kn = 0.f;
#pragma unroll
    for (int d = 0; d < 8; d++) {
        int c = h * 8 + d;
        float g = g_buf[OFF_GAM + (c << 12) + n];
        float bt = g_buf[OFF_BET + (c << 12) + n];
        float q = fmaf(g, g_buf[OFF_QKV + (c << 12) + n], bt) + qb;
        float k = fmaf(g, g_buf[OFF_QKV + ((64 + c) << 12) + n], bt);
        float v = fmaf(g, g_buf[OFF_QKV + ((128 + c) << 12) + n], bt);
        g_buf[OFF_QKVM + (c << 12) + n] = q;
        g_buf[OFF_QKVM + ((64 + c) << 12) + n] = k;
        g_buf[OFF_QKVM + ((128 + c) << 12) + n] = v;
        kn = fmaf(k, k, kn);
    }
    sm[threadIdx.x] = kn;
    __syncthreads();
    for (int st = 128; st > 0; st >>= 1) {
        if (threadIdx.x < st) sm[threadIdx.x] = fmaxf(sm[threadIdx.x], sm[threadIdx.x + st]);
        __syncthreads();
    }
    if (threadIdx.x == 0)
        atomicMax((unsigned int*)&g_buf[OFF_KN + h], __float_as_uint(sm[0]));
}

// ---------------------------------------------------------------------------
// Flash attention, key-pair-packed f32x2 (each lane of the f32x2 handles one
// of two adjacent keys), branch-free bounded softmax (-M folded into the dot
// chain seed), 8 key-splits. Grid (16 qblk, 8 heads, 8 ksplit) = 1024 CTAs,
// 128 thr, 2 queries/thread.
// ---------------------------------------------------------------------------
__global__ void __launch_bounds__(128) attn_kernel() {
    __shared__ __align__(16) float ksi[4096];   // [J][d][par]: u64 idx J*8+d = (k[2J][d],k[2J+1][d])
    __shared__ __align__(16) float vsi[4096];
    const int h = blockIdx.y, z = blockIdx.z;
    const int n0 = blockIdx.x * 256;
    const int tid = threadIdx.x;
    const float* qp = g_buf + OFF_QKVM + (h * 8) * NPIX;
    const float* kp = g_buf + OFF_QKVM + (64 + h * 8) * NPIX;
    const float* vp = g_buf + OFF_QKVM + (128 + h * 8) * NPIX;
    const float kn2 = g_buf[OFF_KN + h];
    const float sc = 0.35355339059327373f * 1.4426950408889634f;  // dh^-0.5 * log2(e)

    u64 q2[2][8], acc2[2][8], negM2[2], l2[2];
#pragma unroll
    for (int i = 0; i < 2; i++) {
        int n = n0 + tid + i * 128;
        float qv[8], qn2 = 0.f;
#pragma unroll
        for (int d = 0; d < 8; d++) { qv[d] = qp[(d << 12) + n] * sc; qn2 = fmaf(qv[d], qv[d], qn2); }
        float M = sqrtf(qn2 * kn2);   // >= any score; identical across splits
        negM2[i] = pack2(-M, -M);
        l2[i] = 0ULL;
#pragma unroll
        for (int d = 0; d < 8; d++) { q2[i][d] = pack2(qv[d], qv[d]); acc2[i][d] = 0ULL; }
    }

    const int jt = z * 512;
    for (int i2 = tid; i2 < 4096; i2 += 128) {
        int d = i2 >> 9, j = i2 & 511;
        int J = j >> 1, par = j & 1;
        ksi[(J * 8 + d) * 2 + par] = kp[(d << 12) + jt + j];
        vsi[(J * 8 + d) * 2 + par] = vp[(d << 12) + jt + j];
    }
    __syncthreads();

    const ulonglong2* kq = (const ulonglong2*)ksi;
    const ulonglong2* vq = (const ulonglong2*)vsi;
    for (int J = 0; J < 256; J++) {
        ulonglong2 k01 = kq[J * 4 + 0], k23 = kq[J * 4 + 1];
        ulonglong2 k45 = kq[J * 4 + 2], k67 = kq[J * 4 + 3];
        ulonglong2 v01 = vq[J * 4 + 0], v23 = vq[J * 4 + 1];
        ulonglong2 v45 = vq[J * 4 + 2], v67 = vq[J * 4 + 3];
#pragma unroll
        for (int i = 0; i < 2; i++) {
            u64 s2 = fma2(q2[i][0], k01.x,
                     fma2(q2[i][1], k01.y,
                     fma2(q2[i][2], k23.x,
                     fma2(q2[i][3], k23.y,
                     fma2(q2[i][4], k45.x,
                     fma2(q2[i][5], k45.y,
                     fma2(q2[i][6], k67.x,
                     fma2(q2[i][7], k67.y, negM2[i]))))))));
            float2 sf = unpack2(s2);
            float pa = ex2f(sf.x);
            float pb = ex2f(sf.y);
            u64 p2 = pack2(pa, pb);
            l2[i] = add2(l2[i], p2);
            acc2[i][0] = fma2(p2, v01.x, acc2[i][0]);
            acc2[i][1] = fma2(p2, v01.y, acc2[i][1]);
            acc2[i][2] = fma2(p2, v23.x, acc2[i][2]);
            acc2[i][3] = fma2(p2, v23.y, acc2[i][3]);
            acc2[i][4] = fma2(p2, v45.x, acc2[i][4]);
            acc2[i][5] = fma2(p2, v45.y, acc2[i][5]);
            acc2[i][6] = fma2(p2, v67.x, acc2[i][6]);
            acc2[i][7] = fma2(p2, v67.y, acc2[i][7]);
        }
    }

    float* pl = g_buf + OFF_PL;
    float* pacc = g_buf + OFF_PACC;
#pragma unroll
    for (int i = 0; i < 2; i++) {
        int n = n0 + tid + i * 128;
        float2 lf = unpack2(l2[i]);
        pl[((z * 8 + h) << 12) + n] = lf.x + lf.y;
#pragma unroll
        for (int d = 0; d < 8; d++) {
            float2 a = unpack2(acc2[i][d]);
            pacc[((z * 64 + h * 8 + d) << 12) + n] = a.x + a.y;
        }
    }
}

// ---------------------------------------------------------------------------
// Fused split-combine + projection GEMM (K=64) + residual. Grid (16, 4),
// 16 output rows per CTA.
// ---------------------------------------------------------------------------
__global__ void __launch_bounds__(256) combineproj_kernel(
        const float* __restrict__ W, const float* __restrict__ bias,
        const float* __restrict__ xres) {
    __shared__ u64 ws2[8 * 64];
    const int row0 = blockIdx.y * 16;
    for (int i = threadIdx.x; i < 512; i += 256) {
        int p = i >> 6, k = i & 63;
        ws2[i] = pack2(W[(row0 + 2 * p) * 64 + k], W[(row0 + 2 * p + 1) * 64 + k]);
    }
    __syncthreads();
    const int n = blockIdx.x * 256 + threadIdx.x;
    const float* pl = g_buf + OFF_PL;
    const float* pacc = g_buf + OFF_PACC;
    float a[64];
#pragma unroll
    for (int h = 0; h < 8; h++) {
        float L = 1e-35f;
#pragma unroll
        for (int s = 0; s < 8; s++) L += pl[((s * 8 + h) << 12) + n];
        float rL = 1.0f / L;
#pragma unroll
        for (int d = 0; d < 8; d++) {
            float o = 0.f;
#pragma unroll
            for (int s = 0; s < 8; s++) o += pacc[((s * 64 + h * 8 + d) << 12) + n];
            a[h * 8 + d] = o * rL;
        }
    }
    u64 acc[8];
#pragma unroll
    for (int p = 0; p < 8; p++) acc[p] = 0ULL;
#pragma unroll 8
    for (int k = 0; k < 64; k++) {
        u64 x2 = pack2(a[k], a[k]);
#pragma unroll
        for (int p = 0; p < 8; p++) acc[p] = fma2(ws2[p * 64 + k], x2, acc[p]);
    }
#pragma unroll
    for (int p = 0; p < 8; p++) {
        float2 v = unpack2(acc[p]);
        int r0 = row0 + 2 * p;
        g_buf[OFF_X2 + (r0 << 12) + n] = v.x + bias[r0] + xres[(r0 << 12) + n];
        g_buf[OFF_X2 + ((r0 + 1) << 12) + n] = v.y + bias[r0 + 1] + xres[((r0 + 1) << 12) + n];
    }
}

// ---------------------------------------------------------------------------
// Depthwise 3x3 conv + exact GELU, one CTA per channel, smem halo tile.
// ---------------------------------------------------------------------------
__global__ void __launch_bounds__(256) dwgelu_kernel(const float* __restrict__ w,
                                                     const float* __restrict__ b) {
    __shared__ float s[66 * 66];
    const int c = blockIdx.x;
    const int tid = threadIdx.x;
    const float* in = g_buf + OFF_Y1 + (c << 12);
    for (int i = tid; i < 66 * 66; i += 256) {
        int yy = i / 66, xx = i - yy * 66;
        int gy = yy - 1, gx = xx - 1;
        float v = 0.f;
        if ((unsigned)gy < 64u && (unsigned)gx < 64u) v = in[gy * 64 + gx];
        s[i] = v;
    }
    __syncthreads();
    float wv[9];
#pragma unroll
    for (int k = 0; k < 9; k++) wv[k] = w[c * 9 + k];
    float bb = b[c];
#pragma unroll 4
    for (int t = 0; t < 16; t++) {
        int n = tid + t * 256;
        int y = n >> 6, x = n & 63;
        float a = bb;
#pragma unroll
        for (int ky = 0; ky < 3; ky++)
#pragma unroll
            for (int kx = 0; kx < 3; kx++)
                a = fmaf(wv[ky * 3 + kx], s[(y + ky) * 66 + x + kx], a);
        g_buf[OFF_Y2 + (c << 12) + n] = 0.5f * a * (1.0f + erff(a * 0.7071067811865476f));
    }
}

// ---------------------------------------------------------------------------
// ffn2: 1x1 conv GEMM K=256 + residual (writes final output).
// ---------------------------------------------------------------------------
__global__ void __launch_bounds__(256) ffn2_kernel(const float* __restrict__ W,
                                                   const float* __restrict__ bias,
                                                   float* __restrict__ Y) {
    __shared__ u64 ws2[8 * 256];
    const int row0 = blockIdx.y * 16;
    for (int i = threadIdx.x; i < 2048; i += 256) {
        int p = i >> 8, k = i & 255;
        ws2[i] = pack2(W[(row0 + 2 * p) * 256 + k], W[(row0 + 2 * p + 1) * 256 + k]);
    }
    __syncthreads();
    const int n = blockIdx.x * 256 + threadIdx.x;
    u64 acc[8];
#pragma unroll
    for (int p = 0; p < 8; p++) acc[p] = 0ULL;
#pragma unroll 8
    for (int k = 0; k < 256; k++) {
        float xv = g_buf[OFF_Y2 + (k << 12) + n];
        u64 x2 = pack2(xv, xv);
#pragma unroll
        for (int p = 0; p < 8; p++) acc[p] = fma2(ws2[p * 256 + k], x2, acc[p]);
    }
#pragma unroll
    for (int p = 0; p < 8; p++) {
        float2 a = unpack2(acc[p]);
        int r0 = row0 + 2 * p;
        Y[(r0 << 12) + n] = a.x + bias[r0] + g_buf[OFF_X2 + (r0 << 12) + n];
        Y[((r0 + 1) << 12) + n] = a.y + bias[r0 + 1] + g_buf[OFF_X2 + ((r0 + 1) << 12) + n];
    }
}

// ---------------------------------------------------------------------------
// Launch
// ---------------------------------------------------------------------------
extern "C" void kernel_launch(void* const* d_in, const int* in_sizes, int n_in,
                              void* d_out, int out_size) {
    const float* x      = (const float*)d_in[0];
    const float* luma   = (const float*)d_in[1];
    const float* ln1_w  = (const float*)d_in[2];
    const float* ln1_b  = (const float*)d_in[3];
    const float* qkv_w  = (const float*)d_in[4];
    const float* qkv_b  = (const float*)d_in[5];
    const float* proj_w = (const float*)d_in[6];
    const float* proj_b = (const float*)d_in[7];
    const float* lc1_w  = (const float*)d_in[8];
    const float* lc1_b  = (const float*)d_in[9];
    const float* lc2_w  = (const float*)d_in[10];
    const float* lc2_b  = (const float*)d_in[11];
    const float* gam_w  = (const float*)d_in[12];
    const float* gam_b  = (const float*)d_in[13];
    const float* bet_w  = (const float*)d_in[14];
    const float* bet_b  = (const float*)d_in[15];
    const float* alpha  = (const float*)d_in[16];
    const float* ln2_w  = (const float*)d_in[17];
    const float* ln2_b  = (const float*)d_in[18];
    const float* ffn1_w = (const float*)d_in[19];
    const float* ffn1_b = (const float*)d_in[20];
    const float* dw_w   = (const float*)d_in[21];
    const float* dw_b   = (const float*)d_in[22];
    const float* ffn2_w = (const float*)d_in[23];
    const float* ffn2_b = (const float*)d_in[24];
    float* out = (float*)d_out;

    float* buf = nullptr;
    cudaGetSymbolAddress((void**)&buf, g_buf);

    ln_gemm_kernel<<<dim3(16, 12), 256>>>(x, ln1_w, ln1_b, qkv_w, qkv_b, buf + OFF_QKV);
    lc_fused_kernel<<<128, 256>>>(luma, lc1_w, lc1_b, lc2_w, lc2_b);
    gambet_pool_kernel<<<dim3(16, 9), 256>>>(gam_w, gam_b, bet_w, bet_b, luma);
    modknorm_kernel<<<dim3(16, 8), 256>>>(alpha);
    attn_kernel<<<dim3(16, 8, 8), 128>>>();
    combineproj_kernel<<<dim3(16, 4), 256>>>(proj_w, proj_b, x);
    ln_gemm_kernel<<<dim3(16, 16), 256>>>(buf + OFF_X2, ln2_w, ln2_b, ffn1_w, ffn1_b, buf + OFF_Y1);
    dwgelu_kernel<<<256, 256>>>(dw_w, dw_b);
    ffn2_kernel<<<dim3(16, 4), 256>>>(ffn2_w, ffn2_b, out);
}